// round 8
// baseline (speedup 1.0000x reference)
#include <cuda_runtime.h>
#include <cuda_bf16.h>
#include <cstdint>

#define BATCH 8
#define NDIM 256      // DIM
#define NHEADS 8
#define DHEAD 64
#define HID 512       // NHEADS*DHEAD
#define NPIX 4096     // 64*64
#define M1 1536       // 3*HID

// ---------------- scratch (device globals; no allocation allowed) ----------
__device__ float g_q[(size_t)BATCH * HID * NPIX];
__device__ float g_k[(size_t)BATCH * HID * NPIX];
__device__ float g_v[(size_t)BATCH * HID * NPIX];
__device__ float g_o[(size_t)BATCH * HID * NPIX];
__device__ float g_kv[(size_t)BATCH * NHEADS * DHEAD * DHEAD];
__device__ float g_ksum[(size_t)BATCH * NHEADS * DHEAD];
__device__ float g_wqkv[(size_t)M1 * NDIM];     // tf32 + k-interleaved Wqkv
__device__ float g_wout[(size_t)NDIM * HID];    // tf32 + k-interleaved Wout

// ---------------- helpers ---------------------------------------------------
__device__ __forceinline__ uint32_t f2tf32(float x) {
    uint32_t r;
    asm("cvt.rna.tf32.f32 %0, %1;" : "=r"(r) : "f"(x));
    return r;
}
__device__ __forceinline__ float f2tf32f(float x) {
    return __uint_as_float(f2tf32(x));
}

__device__ __forceinline__ void mma_tf32(float c[4],
                                         uint32_t a0, uint32_t a1, uint32_t a2, uint32_t a3,
                                         uint32_t b0, uint32_t b1) {
    asm volatile(
        "mma.sync.aligned.m16n8k8.row.col.f32.tf32.tf32.f32 "
        "{%0,%1,%2,%3}, {%4,%5,%6,%7}, {%8,%9}, {%0,%1,%2,%3};"
        : "+f"(c[0]), "+f"(c[1]), "+f"(c[2]), "+f"(c[3])
        : "r"(a0), "r"(a1), "r"(a2), "r"(a3), "r"(b0), "r"(b1));
}

__device__ __forceinline__ void cp16(uint32_t dst_smem, const void* src) {
    asm volatile("cp.async.cg.shared.global [%0], [%1], 16;"
                 :: "r"(dst_smem), "l"(src));
}

// ---------------- weight convert: tf32 round + k-pair interleave ------------
__global__ void convert_w_kernel(const float* __restrict__ src,
                                 float* __restrict__ dst, int total, int K) {
    int i = blockIdx.x * blockDim.x + threadIdx.x;
    if (i < total) {
        int k = i % K;
        int p = k & 7;
        int kd = (k & ~7) + ((p & 3) * 2 + (p >> 2));
        dst[i - k + kd] = f2tf32f(src[i]);
    }
}

// ---------------- K0: zero the kv/ksum accumulators ------------------------
__global__ void zero_acc_kernel() {
    int i = blockIdx.x * blockDim.x + threadIdx.x;
    const int NKV = BATCH * NHEADS * DHEAD * DHEAD;
    const int NKS = BATCH * NHEADS * DHEAD;
    if (i < NKV) g_kv[i] = 0.0f;
    if (i < NKS) g_ksum[i] = 0.0f;
}

// ============================================================================
// tf32 tensor GEMM, cp.async 3-stage. C = A*B. 128x128 tile, BK=16,
// 512 threads = 16 warps, warp grid 4(m)x4(n), warp tile 32x32 (mt=2, nt=4).
// Low regs (~60) -> 2 CTAs/SM = 32 warps resident.
// A smem [128][24] (k-interleaved pairs -> ld.shared.v2); B smem [16][136].
// ============================================================================
#define ASTRIDE 24
#define AST (128 * ASTRIDE)
#define BST (16 * 136)
#define GEMM_SMEM ((3 * AST + 3 * BST) * 4)

template <int KDIM, int EPI>
__global__ __launch_bounds__(512, 2) void gemm_tc_kernel(
    const float* __restrict__ A,      // [M, KDIM] tf32 bits, k-interleaved
    const float* __restrict__ Bbase,  // [BATCH][KDIM][NPIX] fp32 (HW-truncated)
    const float* __restrict__ cm,
    const float* __restrict__ csp,
    const float* __restrict__ bout,
    float* __restrict__ y)
{
    extern __shared__ uint32_t dyn[];
    uint32_t* Asm = dyn;              // [3][128][24]
    uint32_t* Bsm = dyn + 3 * AST;    // [3][16][136]

    const int b     = blockIdx.z;
    const int mBase = blockIdx.y * 128;
    const int nBase = blockIdx.x * 128;
    const float* Bm = Bbase + (size_t)b * KDIM * NPIX;

    const int tid  = threadIdx.x;
    const int wid  = tid >> 5;
    const int lane = tid & 31;
    const int wm   = wid >> 2;          // 0..3 : 32-row slab
    const int wn   = wid & 3;           // 0..3 : 32-col slab
    const int lr   = lane >> 2;
    const int lc   = lane & 3;

    // cp.async mapping (512 threads: one 16B op per tile each)
    const int aRow = tid >> 2;          // 0..127
    const int aSeg = (tid & 3) * 4;
    const int bRow = tid >> 5;          // 0..15
    const int bSeg = (tid & 31) * 4;

    const uint32_t smemBase = (uint32_t)__cvta_generic_to_shared(dyn);
    const float* aSrc = &A[(size_t)(mBase + aRow) * KDIM + aSeg];
    const float* bSrc = &Bm[(size_t)bRow * NPIX + nBase + bSeg];
    const uint32_t aDst = smemBase + (aRow * ASTRIDE + aSeg) * 4;
    const uint32_t bDst = smemBase + (3 * AST + bRow * 136 + bSeg) * 4;

    const int nIter = KDIM / 16;

    #pragma unroll
    for (int s = 0; s < 2; s++) {
        const int k0 = s * 16;
        cp16(aDst + s * AST * 4, aSrc + k0);
        cp16(bDst + s * BST * 4, bSrc + (size_t)k0 * NPIX);
        asm volatile("cp.async.commit_group;");
    }

    float acc[2][4][4];
    #pragma unroll
    for (int mt = 0; mt < 2; mt++)
        #pragma unroll
        for (int nt = 0; nt < 4; nt++)
            #pragma unroll
            for (int i = 0; i < 4; i++) acc[mt][nt][i] = 0.0f;

    int cur = 0;
    for (int it = 0; it < nIter; it++) {
        if (it == nIter - 1)
            asm volatile("cp.async.wait_group 0;");
        else
            asm volatile("cp.async.wait_group 1;");
        __syncthreads();

        const int pf = it + 2;
        if (pf < nIter) {
            const int s = pf % 3;
            const int k0 = pf * 16;
            cp16(aDst + s * AST * 4, aSrc + k0);
            cp16(bDst + s * BST * 4, bSrc + (size_t)k0 * NPIX);
            asm volatile("cp.async.commit_group;");
        }

        const uint32_t* as = Asm + cur * AST;
        const uint32_t* bs = Bsm + cur * BST;
        #pragma unroll
        for (int kk = 0; kk < 16; kk += 8) {
            uint32_t af[2][4];
            #pragma unroll
            for (int mt = 0; mt < 2; mt++) {
                const int m0 = wm * 32 + mt * 16 + lr;
                uint2 lo = *(const uint2*)&as[m0 * ASTRIDE + kk + 2 * lc];
                uint2 hi = *(const uint2*)&as[(m0 + 8) * ASTRIDE + kk + 2 * lc];
                af[mt][0] = lo.x; af[mt][1] = hi.x;
                af[mt][2] = lo.y; af[mt][3] = hi.y;
            }
            #pragma unroll
            for (int nt = 0; nt < 4; nt++) {
                const int n0 = wn * 32 + nt * 8 + lr;
                const uint32_t b0 = bs[(kk + lc) * 136 + n0];
                const uint32_t b1 = bs[(kk + lc + 4) * 136 + n0];
                #pragma unroll
                for (int mt = 0; mt < 2; mt++)
                    mma_tf32(acc[mt][nt], af[mt][0], af[mt][1], af[mt][2], af[mt][3],
                             b0, b1);
            }
        }
        cur++; if (cur == 3) cur = 0;
    }

    // ---------------- epilogue ----------------
    if (EPI == 0) {
        const int grp  = mBase >> 9;         // 0=q, 1=k, 2=v
        const int idx0 = mBase & 511;
        float* dst = (grp == 0) ? g_q : (grp == 1) ? g_k : g_v;
        float* base = dst + ((size_t)b * HID + idx0) * NPIX;
        const float cs = *csp;
        const float* cmb = cm + (size_t)b * NPIX;

        #pragma unroll
        for (int mt = 0; mt < 2; mt++) {
            #pragma unroll
            for (int half = 0; half < 2; half++) {
                const int row = wm * 32 + mt * 16 + lr + half * 8;
                float* drow = base + (size_t)row * NPIX;
                #pragma unroll
                for (int nt = 0; nt < 4; nt++) {
                    const int col = nBase + wn * 32 + nt * 8 + 2 * lc;
                    float v0 = acc[mt][nt][half * 2];
                    float v1 = acc[mt][nt][half * 2 + 1];
                    if (grp < 2) {
                        v0 = (v0 > 0.0f) ? (v0 + 1.0f) : __expf(v0);
                        v1 = (v1 > 0.0f) ? (v1 + 1.0f) : __expf(v1);
                    }
                    if (grp == 1) {
                        v0 *= (1.0f + cs * cmb[col]);
                        v1 *= (1.0f + cs * cmb[col + 1]);
                    }
                    drow[col]     = f2tf32f(v0);
                    drow[col + 1] = f2tf32f(v1);
                }
            }
        }
    } else {
        #pragma unroll
        for (int mt = 0; mt < 2; mt++) {
            #pragma unroll
            for (int half = 0; half < 2; half++) {
                const int row = mBase + wm * 32 + mt * 16 + lr + half * 8;
                const float bias = bout[row];
                float* drow = y + ((size_t)b * NDIM + row) * NPIX;
                #pragma unroll
                for (int nt = 0; nt < 4; nt++) {
                    const int col = nBase + wn * 32 + nt * 8 + 2 * lc;
                    drow[col]     = acc[mt][nt][half * 2]     + bias;
                    drow[col + 1] = acc[mt][nt][half * 2 + 1] + bias;
                }
            }
        }
    }
}

// ============================================================================
// K2 (tensor): kv[d][e] = sum_n k[d][n]*v[e][n]; ksum[d] = sum_n k[d][n].
// ============================================================================
__global__ __launch_bounds__(256) void kv_tc_kernel()
{
    const int pair = blockIdx.y;
    const int b = pair >> 3, h = pair & 7;
    const int n0 = blockIdx.x * 1024;
    const float* kp = g_k + ((size_t)b * HID + h * DHEAD) * NPIX;
    const float* vp = g_v + ((size_t)b * HID + h * DHEAD) * NPIX;

    __shared__ uint32_t ks[64][68];
    __shared__ uint32_t vs[64][68];

    const int tid  = threadIdx.x;
    const int wid  = tid >> 5;
    const int lane = tid & 31;
    const int lr   = lane >> 2;
    const int lc   = lane & 3;
    const int wm   = wid & 3;
    const int wn   = wid >> 2;

    float acc[4][4];
    #pragma unroll
    for (int nt = 0; nt < 4; nt++)
        #pragma unroll
        for (int i = 0; i < 4; i++) acc[nt][i] = 0.0f;
    float ksp[4] = {0.0f, 0.0f, 0.0f, 0.0f};

    for (int t = 0; t < 16; t++) {
        const int nb = n0 + t * 64;
        #pragma unroll
        for (int r = 0; r < 4; r++) {
            int li = tid + r * 256;
            int d  = li >> 4;
            int c4 = (li & 15) * 4;
            float4 kd = *(const float4*)&kp[(size_t)d * NPIX + nb + c4];
            ksp[r] += (kd.x + kd.y) + (kd.z + kd.w);
            *(uint4*)&ks[d][c4] = *(const uint4*)&kd;
            uint4 vd = *(const uint4*)&vp[(size_t)d * NPIX + nb + c4];
            *(uint4*)&vs[d][c4] = vd;
        }
        __syncthreads();
        #pragma unroll
        for (int kk = 0; kk < 64; kk += 8) {
            const int m0 = wm * 16 + lr;
            uint32_t a0 = ks[m0][kk + lc];
            uint32_t a1 = ks[m0 + 8][kk + lc];
            uint32_t a2 = ks[m0][kk + lc + 4];
            uint32_t a3 = ks[m0 + 8][kk + lc + 4];
            #pragma unroll
            for (int nt = 0; nt < 4; nt++) {
                int e0 = wn * 32 + nt * 8 + lr;
                uint32_t b0 = vs[e0][kk + lc];
                uint32_t b1 = vs[e0][kk + lc + 4];
                mma_tf32(acc[nt], a0, a1, a2, a3, b0, b1);
            }
        }
        __syncthreads();
    }

    #pragma unroll
    for (int r = 0; r < 4; r++) {
        float s = ksp[r];
        s += __shfl_xor_sync(0xffffffffu, s, 8);
        s += __shfl_xor_sync(0xffffffffu, s, 4);
        s += __shfl_xor_sync(0xffffffffu, s, 2);
        s += __shfl_xor_sync(0xffffffffu, s, 1);
        if ((tid & 15) == 0)
            atomicAdd(&g_ksum[(size_t)pair * 64 + ((tid + r * 256) >> 4)], s);
    }

    float* kvp = g_kv + (size_t)pair * 4096;
    #pragma unroll
    for (int nt = 0; nt < 4; nt++) {
        int e = wn * 32 + nt * 8 + 2 * lc;
        int d = wm * 16 + lr;
        atomicAdd(&kvp[d * 64 + e],           acc[nt][0]);
        atomicAdd(&kvp[d * 64 + e + 1],       acc[nt][1]);
        atomicAdd(&kvp[(d + 8) * 64 + e],     acc[nt][2]);
        atomicAdd(&kvp[(d + 8) * 64 + e + 1], acc[nt][3]);
    }
}

// ============================================================================
// K3 (tensor): out[e][n] = z[n] * sum_d kv[d][e]*q[d][n]. Writes g_o tf32.
// ============================================================================
__global__ __launch_bounds__(256) void attn_tc_kernel()
{
    extern __shared__ uint32_t dyn[];
    uint32_t* kvt   = dyn;                       // [64][68]
    uint32_t* qs    = dyn + 64 * 68;             // [64][264]
    float*    zs    = (float*)(qs + 64 * 264);   // [256]
    float*    ksums = zs + 256;                  // [64]

    const int pair = blockIdx.y;
    const int b = pair >> 3, h = pair & 7;
    const int nB  = blockIdx.x * 256;
    const int tid = threadIdx.x;
    const int wid = tid >> 5;
    const int lane = tid & 31;
    const int lr = lane >> 2;
    const int lc = lane & 3;

    const float* kvp = g_kv + (size_t)pair * 4096;
    #pragma unroll
    for (int r = 0; r < 16; r++) {
        int i = tid + r * 256;
        int d = i >> 6, e = i & 63;
        kvt[e * 68 + d] = f2tf32(kvp[i]);
    }
    if (tid < 64) ksums[tid] = g_ksum[(size_t)pair * 64 + tid];

    const float* qp = g_q + ((size_t)b * HID + h * DHEAD) * NPIX + nB;
    #pragma unroll
    for (int r = 0; r < 16; r++) {
        int li = tid + r * 256;
        int d  = li >> 6;
        int c4 = (li & 63) * 4;
        uint4 qv = *(const uint4*)&qp[(size_t)d * NPIX + c4];
        *(uint4*)&qs[d * 264 + c4] = qv;
    }
    __syncthreads();

    {
        float denom = 1e-6f;
        #pragma unroll 16
        for (int d = 0; d < 64; d++)
            denom += __uint_as_float(qs[d * 264 + tid]) * ksums[d];
        zs[tid] = 1.0f / denom;
    }
    __syncthreads();

    float acc[4][4][4];
    #pragma unroll
    for (int mt = 0; mt < 4; mt++)
        #pragma unroll
        for (int nt = 0; nt < 4; nt++)
            #pragma unroll
            for (int i = 0; i < 4; i++) acc[mt][nt][i] = 0.0f;

    #pragma unroll
    for (int kk = 0; kk < 64; kk += 8) {
        uint32_t af[4][4];
        #pragma unroll
        for (int mt = 0; mt < 4; mt++) {
            int m0 = mt * 16 + lr;
            af[mt][0] = kvt[m0 * 68 + kk + lc];
            af[mt][1] = kvt[(m0 + 8) * 68 + kk + lc];
            af[mt][2] = kvt[m0 * 68 + kk + lc + 4];
            af[mt][3] = kvt[(m0 + 8) * 68 + kk + lc + 4];
        }
        #pragma unroll
        for (int nt = 0; nt < 4; nt++) {
            int n0 = wid * 32 + nt * 8 + lr;
            uint32_t b0 = qs[(kk + lc) * 264 + n0];
            uint32_t b1 = qs[(kk + lc + 4) * 264 + n0];
            #pragma unroll
            for (int mt = 0; mt < 4; mt++)
                mma_tf32(acc[mt][nt], af[mt][0], af[mt][1], af[mt][2], af[mt][3],
                         b0, b1);
        }
    }

    float* ob = g_o + ((size_t)b * HID + h * DHEAD) * NPIX + nB;
    #pragma unroll
    for (int mt = 0; mt < 4; mt++) {
        #pragma unroll
        for (int half = 0; half < 2; half++) {
            int e = mt * 16 + lr + half * 8;
            float* orow = ob + (size_t)e * NPIX;
            #pragma unroll
            for (int nt = 0; nt < 4; nt++) {
                int nloc = wid * 32 + nt * 8 + 2 * lc;
                orow[nloc]     = f2tf32f(acc[mt][nt][half * 2]     * zs[nloc]);
                orow[nloc + 1] = f2tf32f(acc[mt][nt][half * 2 + 1] * zs[nloc + 1]);
            }
        }
    }
}

// ---------------- launch ----------------------------------------------------
extern "C" void kernel_launch(void* const* d_in, const int* in_sizes, int n_in,
                              void* d_out, int out_size)
{
    const float* x    = (const float*)d_in[0];
    const float* cm   = (const float*)d_in[1];
    const float* Wqkv = (const float*)d_in[2];
    const float* Wout = (const float*)d_in[3];
    const float* bout = (const float*)d_in[4];
    const float* cs   = (const float*)d_in[5];
    float* y = (float*)d_out;

    const int ATTN_SMEM = (64 * 68 + 64 * 264 + 256 + 64) * 4;   // 86272
    cudaFuncSetAttribute(attn_tc_kernel,
                         cudaFuncAttributeMaxDynamicSharedMemorySize, ATTN_SMEM);
    cudaFuncSetAttribute(gemm_tc_kernel<NDIM, 0>,
                         cudaFuncAttributeMaxDynamicSharedMemorySize, GEMM_SMEM);
    cudaFuncSetAttribute(gemm_tc_kernel<HID, 1>,
                         cudaFuncAttributeMaxDynamicSharedMemorySize, GEMM_SMEM);

    float *wqkvt, *woutt, *gobase;
    cudaGetSymbolAddress((void**)&wqkvt, g_wqkv);
    cudaGetSymbolAddress((void**)&woutt, g_wout);
    cudaGetSymbolAddress((void**)&gobase, g_o);

    {
        int n = M1 * NDIM;
        convert_w_kernel<<<(n + 255) / 256, 256>>>(Wqkv, wqkvt, n, NDIM);
        n = NDIM * HID;
        convert_w_kernel<<<(n + 255) / 256, 256>>>(Wout, woutt, n, HID);
    }

    zero_acc_kernel<<<(BATCH * NHEADS * DHEAD * DHEAD + 255) / 256, 256>>>();

    {
        dim3 grid(NPIX / 128, M1 / 128, BATCH);   // 32 x 12 x 8
        gemm_tc_kernel<NDIM, 0><<<grid, 512, GEMM_SMEM>>>(wqkvt, x, cm, cs, nullptr, nullptr);
    }
    {
        dim3 grid(NPIX / 1024, BATCH * NHEADS);   // 4 x 64
        kv_tc_kernel<<<grid, 256>>>();
    }
    {
        dim3 grid(NPIX / 256, BATCH * NHEADS);    // 16 x 64
        attn_tc_kernel<<<grid, 256, ATTN_SMEM>>>();
    }
    {
        dim3 grid(NPIX / 128, NDIM / 128, BATCH); // 32 x 2 x 8
        gemm_tc_kernel<HID, 1><<<grid, 512, GEMM_SMEM>>>(woutt, gobase, nullptr, nullptr, bout, y);
    }
}

// round 12
// speedup vs baseline: 1.5262x; 1.5262x over previous
#include <cuda_runtime.h>
#include <cuda_fp16.h>
#include <cstdint>

#define BATCH 8
#define NDIM 256      // DIM
#define NHEADS 8
#define DHEAD 64
#define HID 512       // NHEADS*DHEAD
#define NPIX 4096     // 64*64
#define M1 1536       // 3*HID

// ---------------- scratch (device globals; no allocation allowed) ----------
__device__ float  g_q[(size_t)BATCH * HID * NPIX];
__device__ float  g_k[(size_t)BATCH * HID * NPIX];
__device__ float  g_v[(size_t)BATCH * HID * NPIX];
__device__ __half g_oh[(size_t)BATCH * HID * NPIX];     // attn out, half
__device__ __half g_xh[(size_t)BATCH * NDIM * NPIX];    // x, half
__device__ __half g_wqkvh[(size_t)M1 * NDIM];           // Wqkv, half
__device__ __half g_wouth[(size_t)NDIM * HID];          // Wout, half
__device__ float  g_kv[(size_t)BATCH * NHEADS * DHEAD * DHEAD];
__device__ float  g_ksum[(size_t)BATCH * NHEADS * DHEAD];

// ---------------- helpers ---------------------------------------------------
__device__ __forceinline__ uint32_t f2tf32(float x) {
    uint32_t r;
    asm("cvt.rna.tf32.f32 %0, %1;" : "=r"(r) : "f"(x));
    return r;
}
__device__ __forceinline__ float f2tf32f(float x) {
    return __uint_as_float(f2tf32(x));
}

__device__ __forceinline__ void mma_tf32(float c[4],
                                         uint32_t a0, uint32_t a1, uint32_t a2, uint32_t a3,
                                         uint32_t b0, uint32_t b1) {
    asm volatile(
        "mma.sync.aligned.m16n8k8.row.col.f32.tf32.tf32.f32 "
        "{%0,%1,%2,%3}, {%4,%5,%6,%7}, {%8,%9}, {%0,%1,%2,%3};"
        : "+f"(c[0]), "+f"(c[1]), "+f"(c[2]), "+f"(c[3])
        : "r"(a0), "r"(a1), "r"(a2), "r"(a3), "r"(b0), "r"(b1));
}

__device__ __forceinline__ void mma_f16(float c[4],
                                        uint32_t a0, uint32_t a1, uint32_t a2, uint32_t a3,
                                        uint32_t b0, uint32_t b1) {
    asm volatile(
        "mma.sync.aligned.m16n8k16.row.col.f32.f16.f16.f32 "
        "{%0,%1,%2,%3}, {%4,%5,%6,%7}, {%8,%9}, {%0,%1,%2,%3};"
        : "+f"(c[0]), "+f"(c[1]), "+f"(c[2]), "+f"(c[3])
        : "r"(a0), "r"(a1), "r"(a2), "r"(a3), "r"(b0), "r"(b1));
}

__device__ __forceinline__ void ldm_x4(uint32_t& r0, uint32_t& r1,
                                       uint32_t& r2, uint32_t& r3, uint32_t addr) {
    asm volatile("ldmatrix.sync.aligned.m8n8.x4.shared.b16 {%0,%1,%2,%3}, [%4];"
                 : "=r"(r0), "=r"(r1), "=r"(r2), "=r"(r3) : "r"(addr));
}
__device__ __forceinline__ void ldm_x4t(uint32_t& r0, uint32_t& r1,
                                        uint32_t& r2, uint32_t& r3, uint32_t addr) {
    asm volatile("ldmatrix.sync.aligned.m8n8.x4.trans.shared.b16 {%0,%1,%2,%3}, [%4];"
                 : "=r"(r0), "=r"(r1), "=r"(r2), "=r"(r3) : "r"(addr));
}

__device__ __forceinline__ void cp16(uint32_t dst_smem, const void* src) {
    asm volatile("cp.async.cg.shared.global [%0], [%1], 16;"
                 :: "r"(dst_smem), "l"(src));
}

// ---------------- converts ---------------------------------------------------
__global__ void f32_to_f16_kernel(const float4* __restrict__ src,
                                  __half2* __restrict__ dst, int n4) {
    int i = blockIdx.x * blockDim.x + threadIdx.x;
    if (i < n4) {
        float4 v = src[i];
        dst[2 * i]     = __floats2half2_rn(v.x, v.y);
        dst[2 * i + 1] = __floats2half2_rn(v.z, v.w);
    }
}

// ---------------- K0: zero the kv/ksum accumulators ------------------------
__global__ void zero_acc_kernel() {
    int i = blockIdx.x * blockDim.x + threadIdx.x;
    const int NKV = BATCH * NHEADS * DHEAD * DHEAD;
    const int NKS = BATCH * NHEADS * DHEAD;
    if (i < NKV) g_kv[i] = 0.0f;
    if (i < NKS) g_ksum[i] = 0.0f;
}

// ============================================================================
// fp16 tensor GEMM, cp.async 3-stage, ldmatrix + m16n8k16.
// C[M,N] = A[M,K]*B[K,N]. 128x128 tile, BK=32, 256 threads, 8 warps,
// warp grid 2(m)x4(n), warp tile 64x32.
// A smem rows 80 B; B smem rows 272 B (both conflict-free for ldmatrix).
// Staging per 32-K step: A = 2 cp16/thread (128 rows x 64 B),
//                        B = 2 cp16/thread (32 rows x 256 B).
// ============================================================================
#define ASTG 10240            // 128 * 80 B
#define BSTG 8704             // 32 * 272 B
#define STG  (ASTG + BSTG)    // 18944
#define GEMM_SMEM (3 * STG)   // 56832

template <int KDIM, int EPI>
__global__ __launch_bounds__(256, 2) void gemm_f16_kernel(
    const __half* __restrict__ A,      // [M, KDIM] half
    const __half* __restrict__ Bbase,  // [BATCH][KDIM][NPIX] half
    const float* __restrict__ cm,
    const float* __restrict__ csp,
    const float* __restrict__ bout,
    float* __restrict__ y)
{
    extern __shared__ uint8_t smem[];

    const int b     = blockIdx.z;
    const int mBase = blockIdx.y * 128;
    const int nBase = blockIdx.x * 128;
    const __half* Bm = Bbase + (size_t)b * KDIM * NPIX;

    const int tid  = threadIdx.x;
    const int wid  = tid >> 5;
    const int lane = tid & 31;
    const int wm   = wid >> 2;          // 0..1 : 64-row slab
    const int wn   = wid & 3;           // 0..3 : 32-col slab
    const int lr   = lane >> 2;
    const int lc   = lane & 3;

    // staging maps
    const int aRow = tid >> 2;          // 0..63 (+64)
    const int aCh  = tid & 3;           // 4 x 16B = 64B row data
    const int bRow = tid >> 4;          // 0..15 (+16)
    const int bCh  = tid & 15;          // 16 x 16B = 256B row data

    const uint32_t sb = (uint32_t)__cvta_generic_to_shared(smem);
    const __half* aSrc0 = &A[(size_t)(mBase + aRow) * KDIM + aCh * 8];
    const __half* aSrc1 = &A[(size_t)(mBase + aRow + 64) * KDIM + aCh * 8];
    const __half* bSrc0 = &Bm[(size_t)bRow * NPIX + nBase + bCh * 8];
    const __half* bSrc1 = &Bm[(size_t)(bRow + 16) * NPIX + nBase + bCh * 8];
    const uint32_t aDst0 = sb + aRow * 80 + aCh * 16;
    const uint32_t aDst1 = sb + (aRow + 64) * 80 + aCh * 16;
    const uint32_t bDst0 = sb + ASTG + bRow * 272 + bCh * 16;
    const uint32_t bDst1 = sb + ASTG + (bRow + 16) * 272 + bCh * 16;

    // ldmatrix lane bases
    const uint32_t aLm = sb + (wm * 64 + (lane & 15)) * 80 + (lane >> 4) * 16;
    const uint32_t bLm = sb + ASTG + (lane & 15) * 272 + (wn * 32 + (lane >> 4) * 8) * 2;

    const int nIter = KDIM / 32;

    #pragma unroll
    for (int s = 0; s < 2; s++) {
        const int k0 = s * 32;
        cp16(aDst0 + s * STG, aSrc0 + k0);
        cp16(aDst1 + s * STG, aSrc1 + k0);
        cp16(bDst0 + s * STG, bSrc0 + (size_t)k0 * NPIX);
        cp16(bDst1 + s * STG, bSrc1 + (size_t)k0 * NPIX);
        asm volatile("cp.async.commit_group;");
    }

    float acc[4][4][4];
    #pragma unroll
    for (int mt = 0; mt < 4; mt++)
        #pragma unroll
        for (int nt = 0; nt < 4; nt++)
            #pragma unroll
            for (int i = 0; i < 4; i++) acc[mt][nt][i] = 0.0f;

    int cur = 0;
    for (int it = 0; it < nIter; it++) {
        if (it == nIter - 1)
            asm volatile("cp.async.wait_group 0;");
        else
            asm volatile("cp.async.wait_group 1;");
        __syncthreads();

        const int pf = it + 2;
        if (pf < nIter) {
            const int s = pf % 3;
            const int k0 = pf * 32;
            cp16(aDst0 + s * STG, aSrc0 + k0);
            cp16(aDst1 + s * STG, aSrc1 + k0);
            cp16(bDst0 + s * STG, bSrc0 + (size_t)k0 * NPIX);
            cp16(bDst1 + s * STG, bSrc1 + (size_t)k0 * NPIX);
            asm volatile("cp.async.commit_group;");
        }

        const uint32_t aS = aLm + cur * STG;
        const uint32_t bS = bLm + cur * STG;
        #pragma unroll
        for (int kk = 0; kk < 2; kk++) {           // two k16 steps
            uint32_t af[4][4];
            #pragma unroll
            for (int mt = 0; mt < 4; mt++)
                ldm_x4(af[mt][0], af[mt][1], af[mt][2], af[mt][3],
                       aS + mt * 16 * 80 + kk * 32);
            uint32_t bf[4][2];
            #pragma unroll
            for (int g = 0; g < 2; g++)            // two n16 groups
                ldm_x4t(bf[2 * g][0], bf[2 * g][1], bf[2 * g + 1][0], bf[2 * g + 1][1],
                        bS + kk * 16 * 272 + g * 32);
            #pragma unroll
            for (int nt = 0; nt < 4; nt++)
                #pragma unroll
                for (int mt = 0; mt < 4; mt++)
                    mma_f16(acc[mt][nt], af[mt][0], af[mt][1], af[mt][2], af[mt][3],
                            bf[nt][0], bf[nt][1]);
        }
        cur++; if (cur == 3) cur = 0;
    }

    // ---------------- epilogue ----------------
    if (EPI == 0) {
        const int grp  = mBase >> 9;         // 0=q, 1=k, 2=v
        const int idx0 = mBase & 511;
        float* dst = (grp == 0) ? g_q : (grp == 1) ? g_k : g_v;
        float* base = dst + ((size_t)b * HID + idx0) * NPIX;
        const float cs = *csp;
        const float* cmb = cm + (size_t)b * NPIX;

        #pragma unroll
        for (int mt = 0; mt < 4; mt++) {
            #pragma unroll
            for (int half = 0; half < 2; half++) {
                const int row = wm * 64 + mt * 16 + lr + half * 8;
                float* drow = base + (size_t)row * NPIX;
                #pragma unroll
                for (int nt = 0; nt < 4; nt++) {
                    const int col = nBase + wn * 32 + nt * 8 + 2 * lc;
                    float v0 = acc[mt][nt][half * 2];
                    float v1 = acc[mt][nt][half * 2 + 1];
                    if (grp < 2) {
                        v0 = (v0 > 0.0f) ? (v0 + 1.0f) : __expf(v0);
                        v1 = (v1 > 0.0f) ? (v1 + 1.0f) : __expf(v1);
                    }
                    if (grp == 1) {
                        v0 *= (1.0f + cs * cmb[col]);
                        v1 *= (1.0f + cs * cmb[col + 1]);
                    }
                    drow[col]     = f2tf32f(v0);
                    drow[col + 1] = f2tf32f(v1);
                }
            }
        }
    } else {
        #pragma unroll
        for (int mt = 0; mt < 4; mt++) {
            #pragma unroll
            for (int half = 0; half < 2; half++) {
                const int row = mBase + wm * 64 + mt * 16 + lr + half * 8;
                const float bias = bout[row];
                float* drow = y + ((size_t)b * NDIM + row) * NPIX;
                #pragma unroll
                for (int nt = 0; nt < 4; nt++) {
                    const int col = nBase + wn * 32 + nt * 8 + 2 * lc;
                    drow[col]     = acc[mt][nt][half * 2]     + bias;
                    drow[col + 1] = acc[mt][nt][half * 2 + 1] + bias;
                }
            }
        }
    }
}

// ============================================================================
// K2 (tensor): kv[d][e] = sum_n k[d][n]*v[e][n]; ksum[d] = sum_n k[d][n].
// ============================================================================
__global__ __launch_bounds__(256) void kv_tc_kernel()
{
    const int pair = blockIdx.y;
    const int b = pair >> 3, h = pair & 7;
    const int n0 = blockIdx.x * 1024;
    const float* kp = g_k + ((size_t)b * HID + h * DHEAD) * NPIX;
    const float* vp = g_v + ((size_t)b * HID + h * DHEAD) * NPIX;

    __shared__ uint32_t ks[64][68];
    __shared__ uint32_t vs[64][68];

    const int tid  = threadIdx.x;
    const int wid  = tid >> 5;
    const int lane = tid & 31;
    const int lr   = lane >> 2;
    const int lc   = lane & 3;
    const int wm   = wid & 3;
    const int wn   = wid >> 2;

    float acc[4][4];
    #pragma unroll
    for (int nt = 0; nt < 4; nt++)
        #pragma unroll
        for (int i = 0; i < 4; i++) acc[nt][i] = 0.0f;
    float ksp[4] = {0.0f, 0.0f, 0.0f, 0.0f};

    for (int t = 0; t < 16; t++) {
        const int nb = n0 + t * 64;
        #pragma unroll
        for (int r = 0; r < 4; r++) {
            int li = tid + r * 256;
            int d  = li >> 4;
            int c4 = (li & 15) * 4;
            float4 kd = *(const float4*)&kp[(size_t)d * NPIX + nb + c4];
            ksp[r] += (kd.x + kd.y) + (kd.z + kd.w);
            *(uint4*)&ks[d][c4] = *(const uint4*)&kd;
            uint4 vd = *(const uint4*)&vp[(size_t)d * NPIX + nb + c4];
            *(uint4*)&vs[d][c4] = vd;
        }
        __syncthreads();
        #pragma unroll
        for (int kk = 0; kk < 64; kk += 8) {
            const int m0 = wm * 16 + lr;
            uint32_t a0 = ks[m0][kk + lc];
            uint32_t a1 = ks[m0 + 8][kk + lc];
            uint32_t a2 = ks[m0][kk + lc + 4];
            uint32_t a3 = ks[m0 + 8][kk + lc + 4];
            #pragma unroll
            for (int nt = 0; nt < 4; nt++) {
                int e0 = wn * 32 + nt * 8 + lr;
                uint32_t b0 = vs[e0][kk + lc];
                uint32_t b1 = vs[e0][kk + lc + 4];
                mma_tf32(acc[nt], a0, a1, a2, a3, b0, b1);
            }
        }
        __syncthreads();
    }

    #pragma unroll
    for (int r = 0; r < 4; r++) {
        float s = ksp[r];
        s += __shfl_xor_sync(0xffffffffu, s, 8);
        s += __shfl_xor_sync(0xffffffffu, s, 4);
        s += __shfl_xor_sync(0xffffffffu, s, 2);
        s += __shfl_xor_sync(0xffffffffu, s, 1);
        if ((tid & 15) == 0)
            atomicAdd(&g_ksum[(size_t)pair * 64 + ((tid + r * 256) >> 4)], s);
    }

    float* kvp = g_kv + (size_t)pair * 4096;
    #pragma unroll
    for (int nt = 0; nt < 4; nt++) {
        int e = wn * 32 + nt * 8 + 2 * lc;
        int d = wm * 16 + lr;
        atomicAdd(&kvp[d * 64 + e],           acc[nt][0]);
        atomicAdd(&kvp[d * 64 + e + 1],       acc[nt][1]);
        atomicAdd(&kvp[(d + 8) * 64 + e],     acc[nt][2]);
        atomicAdd(&kvp[(d + 8) * 64 + e + 1], acc[nt][3]);
    }
}

// ============================================================================
// K3 (tensor): out[e][n] = z[n] * sum_d kv[d][e]*q[d][n]. Writes g_oh (half).
// ============================================================================
__global__ __launch_bounds__(256) void attn_tc_kernel()
{
    extern __shared__ uint32_t dyn[];
    uint32_t* kvt   = dyn;                       // [64][68]
    uint32_t* qs    = dyn + 64 * 68;             // [64][264]
    float*    zs    = (float*)(qs + 64 * 264);   // [256]
    float*    ksums = zs + 256;                  // [64]

    const int pair = blockIdx.y;
    const int b = pair >> 3, h = pair & 7;
    const int nB  = blockIdx.x * 256;
    const int tid = threadIdx.x;
    const int wid = tid >> 5;
    const int lane = tid & 31;
    const int lr = lane >> 2;
    const int lc = lane & 3;

    const float* kvp = g_kv + (size_t)pair * 4096;
    #pragma unroll
    for (int r = 0; r < 16; r++) {
        int i = tid + r * 256;
        int d = i >> 6, e = i & 63;
        kvt[e * 68 + d] = f2tf32(kvp[i]);
    }
    if (tid < 64) ksums[tid] = g_ksum[(size_t)pair * 64 + tid];

    const float* qp = g_q + ((size_t)b * HID + h * DHEAD) * NPIX + nB;
    #pragma unroll
    for (int r = 0; r < 16; r++) {
        int li = tid + r * 256;
        int d  = li >> 6;
        int c4 = (li & 63) * 4;
        uint4 qv = *(const uint4*)&qp[(size_t)d * NPIX + c4];
        *(uint4*)&qs[d * 264 + c4] = qv;
    }
    __syncthreads();

    {
        float denom = 1e-6f;
        #pragma unroll 16
        for (int d = 0; d < 64; d++)
            denom += __uint_as_float(qs[d * 264 + tid]) * ksums[d];
        zs[tid] = 1.0f / denom;
    }
    __syncthreads();

    float acc[4][4][4];
    #pragma unroll
    for (int mt = 0; mt < 4; mt++)
        #pragma unroll
        for (int nt = 0; nt < 4; nt++)
            #pragma unroll
            for (int i = 0; i < 4; i++) acc[mt][nt][i] = 0.0f;

    #pragma unroll
    for (int kk = 0; kk < 64; kk += 8) {
        uint32_t af[4][4];
        #pragma unroll
        for (int mt = 0; mt < 4; mt++) {
            int m0 = mt * 16 + lr;
            af[mt][0] = kvt[m0 * 68 + kk + lc];
            af[mt][1] = kvt[(m0 + 8) * 68 + kk + lc];
            af[mt][2] = kvt[m0 * 68 + kk + lc + 4];
            af[mt][3] = kvt[(m0 + 8) * 68 + kk + lc + 4];
        }
        #pragma unroll
        for (int nt = 0; nt < 4; nt++) {
            int n0 = wid * 32 + nt * 8 + lr;
            uint32_t b0 = qs[(kk + lc) * 264 + n0];
            uint32_t b1 = qs[(kk + lc + 4) * 264 + n0];
            #pragma unroll
            for (int mt = 0; mt < 4; mt++)
                mma_tf32(acc[mt][nt], af[mt][0], af[mt][1], af[mt][2], af[mt][3],
                         b0, b1);
        }
    }

    __half* ob = g_oh + ((size_t)b * HID + h * DHEAD) * NPIX + nB;
    #pragma unroll
    for (int mt = 0; mt < 4; mt++) {
        #pragma unroll
        for (int half = 0; half < 2; half++) {
            int e = mt * 16 + lr + half * 8;
            __half* orow = ob + (size_t)e * NPIX;
            #pragma unroll
            for (int nt = 0; nt < 4; nt++) {
                int nloc = wid * 32 + nt * 8 + 2 * lc;
                *(__half2*)&orow[nloc] = __floats2half2_rn(
                    acc[mt][nt][half * 2]     * zs[nloc],
                    acc[mt][nt][half * 2 + 1] * zs[nloc + 1]);
            }
        }
    }
}

// ---------------- launch ----------------------------------------------------
extern "C" void kernel_launch(void* const* d_in, const int* in_sizes, int n_in,
                              void* d_out, int out_size)
{
    const float* x    = (const float*)d_in[0];
    const float* cm   = (const float*)d_in[1];
    const float* Wqkv = (const float*)d_in[2];
    const float* Wout = (const float*)d_in[3];
    const float* bout = (const float*)d_in[4];
    const float* cs   = (const float*)d_in[5];
    float* y = (float*)d_out;

    const int ATTN_SMEM = (64 * 68 + 64 * 264 + 256 + 64) * 4;   // 86272
    cudaFuncSetAttribute(attn_tc_kernel,
                         cudaFuncAttributeMaxDynamicSharedMemorySize, ATTN_SMEM);
    cudaFuncSetAttribute(gemm_f16_kernel<NDIM, 0>,
                         cudaFuncAttributeMaxDynamicSharedMemorySize, GEMM_SMEM);
    cudaFuncSetAttribute(gemm_f16_kernel<HID, 1>,
                         cudaFuncAttributeMaxDynamicSharedMemorySize, GEMM_SMEM);

    __half *xh, *wqkvh, *wouth, *oh;
    cudaGetSymbolAddress((void**)&xh, g_xh);
    cudaGetSymbolAddress((void**)&wqkvh, g_wqkvh);
    cudaGetSymbolAddress((void**)&wouth, g_wouth);
    cudaGetSymbolAddress((void**)&oh, g_oh);

    // fp16 pre-converts
    {
        int n4 = BATCH * NDIM * NPIX / 4;
        f32_to_f16_kernel<<<(n4 + 255) / 256, 256>>>((const float4*)x, (__half2*)xh, n4);
        n4 = M1 * NDIM / 4;
        f32_to_f16_kernel<<<(n4 + 255) / 256, 256>>>((const float4*)Wqkv, (__half2*)wqkvh, n4);
        n4 = NDIM * HID / 4;
        f32_to_f16_kernel<<<(n4 + 255) / 256, 256>>>((const float4*)Wout, (__half2*)wouth, n4);
    }

    zero_acc_kernel<<<(BATCH * NHEADS * DHEAD * DHEAD + 255) / 256, 256>>>();

    {
        dim3 grid(NPIX / 128, M1 / 128, BATCH);   // 32 x 12 x 8
        gemm_f16_kernel<NDIM, 0><<<grid, 256, GEMM_SMEM>>>(wqkvh, xh, cm, cs, nullptr, nullptr);
    }
    {
        dim3 grid(NPIX / 1024, BATCH * NHEADS);   // 4 x 64
        kv_tc_kernel<<<grid, 256>>>();
    }
    {
        dim3 grid(NPIX / 256, BATCH * NHEADS);    // 16 x 64
        attn_tc_kernel<<<grid, 256, ATTN_SMEM>>>();
    }
    {
        dim3 grid(NPIX / 128, NDIM / 128, BATCH); // 32 x 2 x 8
        gemm_f16_kernel<HID, 1><<<grid, 256, GEMM_SMEM>>>(wouth, oh, nullptr, nullptr, bout, y);
    }
}

// round 16
// speedup vs baseline: 1.9694x; 1.2904x over previous
#include <cuda_runtime.h>
#include <cuda_fp16.h>
#include <cstdint>

#define BATCH 8
#define NDIM 256      // DIM
#define NHEADS 8
#define DHEAD 64
#define HID 512       // NHEADS*DHEAD
#define NPIX 4096     // 64*64
#define M1 1536       // 3*HID

// ---------------- scratch (device globals; no allocation allowed) ----------
__device__ __half g_qh[(size_t)BATCH * HID * NPIX];
__device__ __half g_kh[(size_t)BATCH * HID * NPIX];
__device__ __half g_vh[(size_t)BATCH * HID * NPIX];
__device__ __half g_oh[(size_t)BATCH * HID * NPIX];
__device__ __half g_xh[(size_t)BATCH * NDIM * NPIX];
__device__ __half g_wqkvh[(size_t)M1 * NDIM];
__device__ __half g_wouth[(size_t)NDIM * HID];
__device__ float  g_kv[(size_t)BATCH * NHEADS * DHEAD * DHEAD];   // [pair][d][e]
__device__ float  g_ksum[(size_t)BATCH * NHEADS * DHEAD];

// ---------------- helpers ---------------------------------------------------
__device__ __forceinline__ void mma_f16(float c[4],
                                        uint32_t a0, uint32_t a1, uint32_t a2, uint32_t a3,
                                        uint32_t b0, uint32_t b1) {
    asm volatile(
        "mma.sync.aligned.m16n8k16.row.col.f32.f16.f16.f32 "
        "{%0,%1,%2,%3}, {%4,%5,%6,%7}, {%8,%9}, {%0,%1,%2,%3};"
        : "+f"(c[0]), "+f"(c[1]), "+f"(c[2]), "+f"(c[3])
        : "r"(a0), "r"(a1), "r"(a2), "r"(a3), "r"(b0), "r"(b1));
}

__device__ __forceinline__ void ldm_x4(uint32_t& r0, uint32_t& r1,
                                       uint32_t& r2, uint32_t& r3, uint32_t addr) {
    asm volatile("ldmatrix.sync.aligned.m8n8.x4.shared.b16 {%0,%1,%2,%3}, [%4];"
                 : "=r"(r0), "=r"(r1), "=r"(r2), "=r"(r3) : "r"(addr));
}
__device__ __forceinline__ void ldm_x4t(uint32_t& r0, uint32_t& r1,
                                        uint32_t& r2, uint32_t& r3, uint32_t addr) {
    asm volatile("ldmatrix.sync.aligned.m8n8.x4.trans.shared.b16 {%0,%1,%2,%3}, [%4];"
                 : "=r"(r0), "=r"(r1), "=r"(r2), "=r"(r3) : "r"(addr));
}

__device__ __forceinline__ void cp16(uint32_t dst_smem, const void* src) {
    asm volatile("cp.async.cg.shared.global [%0], [%1], 16;"
                 :: "r"(dst_smem), "l"(src));
}

// ---------------- converts ---------------------------------------------------
// x convert + zero accumulators fused (n4 = 2M threads > NKV)
__global__ void convert_x_zero_kernel(const float4* __restrict__ src,
                                      __half2* __restrict__ dst, int n4) {
    int i = blockIdx.x * blockDim.x + threadIdx.x;
    if (i < n4) {
        float4 v = src[i];
        dst[2 * i]     = __floats2half2_rn(v.x, v.y);
        dst[2 * i + 1] = __floats2half2_rn(v.z, v.w);
    }
    const int NKV = BATCH * NHEADS * DHEAD * DHEAD;
    const int NKS = BATCH * NHEADS * DHEAD;
    if (i < NKV) g_kv[i] = 0.0f;
    if (i < NKS) g_ksum[i] = 0.0f;
}

__global__ void f32_to_f16_kernel(const float4* __restrict__ src,
                                  __half2* __restrict__ dst, int n4) {
    int i = blockIdx.x * blockDim.x + threadIdx.x;
    if (i < n4) {
        float4 v = src[i];
        dst[2 * i]     = __floats2half2_rn(v.x, v.y);
        dst[2 * i + 1] = __floats2half2_rn(v.z, v.w);
    }
}

// ============================================================================
// fp16 tensor GEMM, cp.async 3-stage, ldmatrix + m16n8k16.
// C[M,N] = A[M,K]*B[K,N]. 128x128 tile, BK=32, 256 threads, 8 warps,
// warp grid 2(m)x4(n), warp tile 64x32.
// ============================================================================
#define ASTG 10240            // 128 * 80 B
#define BSTG 8704             // 32 * 272 B
#define STG  (ASTG + BSTG)    // 18944
#define GEMM_SMEM (3 * STG)   // 56832

template <int KDIM, int EPI>
__global__ __launch_bounds__(256, 2) void gemm_f16_kernel(
    const __half* __restrict__ A,      // [M, KDIM] half
    const __half* __restrict__ Bbase,  // [BATCH][KDIM][NPIX] half
    const float* __restrict__ cm,
    const float* __restrict__ csp,
    const float* __restrict__ bout,
    float* __restrict__ y)
{
    extern __shared__ uint8_t smem[];

    const int b     = blockIdx.z;
    const int mBase = blockIdx.y * 128;
    const int nBase = blockIdx.x * 128;
    const __half* Bm = Bbase + (size_t)b * KDIM * NPIX;

    const int tid  = threadIdx.x;
    const int wid  = tid >> 5;
    const int lane = tid & 31;
    const int wm   = wid >> 2;          // 0..1 : 64-row slab
    const int wn   = wid & 3;           // 0..3 : 32-col slab
    const int lr   = lane >> 2;
    const int lc   = lane & 3;

    const int aRow = tid >> 2;          // 0..63 (+64)
    const int aCh  = tid & 3;
    const int bRow = tid >> 4;          // 0..15 (+16)
    const int bCh  = tid & 15;

    const uint32_t sb = (uint32_t)__cvta_generic_to_shared(smem);
    const __half* aSrc0 = &A[(size_t)(mBase + aRow) * KDIM + aCh * 8];
    const __half* aSrc1 = &A[(size_t)(mBase + aRow + 64) * KDIM + aCh * 8];
    const __half* bSrc0 = &Bm[(size_t)bRow * NPIX + nBase + bCh * 8];
    const __half* bSrc1 = &Bm[(size_t)(bRow + 16) * NPIX + nBase + bCh * 8];
    const uint32_t aDst0 = sb + aRow * 80 + aCh * 16;
    const uint32_t aDst1 = sb + (aRow + 64) * 80 + aCh * 16;
    const uint32_t bDst0 = sb + ASTG + bRow * 272 + bCh * 16;
    const uint32_t bDst1 = sb + ASTG + (bRow + 16) * 272 + bCh * 16;

    const uint32_t aLm = sb + (wm * 64 + (lane & 15)) * 80 + (lane >> 4) * 16;
    const uint32_t bLm = sb + ASTG + (lane & 15) * 272 + (wn * 32 + (lane >> 4) * 8) * 2;

    const int nIter = KDIM / 32;

    #pragma unroll
    for (int s = 0; s < 2; s++) {
        const int k0 = s * 32;
        cp16(aDst0 + s * STG, aSrc0 + k0);
        cp16(aDst1 + s * STG, aSrc1 + k0);
        cp16(bDst0 + s * STG, bSrc0 + (size_t)k0 * NPIX);
        cp16(bDst1 + s * STG, bSrc1 + (size_t)k0 * NPIX);
        asm volatile("cp.async.commit_group;");
    }

    float acc[4][4][4];
    #pragma unroll
    for (int mt = 0; mt < 4; mt++)
        #pragma unroll
        for (int nt = 0; nt < 4; nt++)
            #pragma unroll
            for (int i = 0; i < 4; i++) acc[mt][nt][i] = 0.0f;

    int cur = 0;
    for (int it = 0; it < nIter; it++) {
        if (it == nIter - 1)
            asm volatile("cp.async.wait_group 0;");
        else
            asm volatile("cp.async.wait_group 1;");
        __syncthreads();

        const int pf = it + 2;
        if (pf < nIter) {
            const int s = pf % 3;
            const int k0 = pf * 32;
            cp16(aDst0 + s * STG, aSrc0 + k0);
            cp16(aDst1 + s * STG, aSrc1 + k0);
            cp16(bDst0 + s * STG, bSrc0 + (size_t)k0 * NPIX);
            cp16(bDst1 + s * STG, bSrc1 + (size_t)k0 * NPIX);
            asm volatile("cp.async.commit_group;");
        }

        const uint32_t aS = aLm + cur * STG;
        const uint32_t bS = bLm + cur * STG;
        #pragma unroll
        for (int kk = 0; kk < 2; kk++) {
            uint32_t af[4][4];
            #pragma unroll
            for (int mt = 0; mt < 4; mt++)
                ldm_x4(af[mt][0], af[mt][1], af[mt][2], af[mt][3],
                       aS + mt * 16 * 80 + kk * 32);
            uint32_t bf[4][2];
            #pragma unroll
            for (int g = 0; g < 2; g++)
                ldm_x4t(bf[2 * g][0], bf[2 * g][1], bf[2 * g + 1][0], bf[2 * g + 1][1],
                        bS + kk * 16 * 272 + g * 32);
            #pragma unroll
            for (int nt = 0; nt < 4; nt++)
                #pragma unroll
                for (int mt = 0; mt < 4; mt++)
                    mma_f16(acc[mt][nt], af[mt][0], af[mt][1], af[mt][2], af[mt][3],
                            bf[nt][0], bf[nt][1]);
        }
        cur++; if (cur == 3) cur = 0;
    }

    // ---------------- epilogue ----------------
    if (EPI == 0) {
        const int grp  = mBase >> 9;         // 0=q, 1=k, 2=v
        const int idx0 = mBase & 511;
        __half* dst = (grp == 0) ? g_qh : (grp == 1) ? g_kh : g_vh;
        __half* base = dst + ((size_t)b * HID + idx0) * NPIX;
        const float cs = *csp;
        const float* cmb = cm + (size_t)b * NPIX;

        #pragma unroll
        for (int mt = 0; mt < 4; mt++) {
            #pragma unroll
            for (int half = 0; half < 2; half++) {
                const int row = wm * 64 + mt * 16 + lr + half * 8;
                __half* drow = base + (size_t)row * NPIX;
                #pragma unroll
                for (int nt = 0; nt < 4; nt++) {
                    const int col = nBase + wn * 32 + nt * 8 + 2 * lc;
                    float v0 = acc[mt][nt][half * 2];
                    float v1 = acc[mt][nt][half * 2 + 1];
                    if (grp < 2) {
                        v0 = (v0 > 0.0f) ? (v0 + 1.0f) : __expf(v0);
                        v1 = (v1 > 0.0f) ? (v1 + 1.0f) : __expf(v1);
                    }
                    if (grp == 1) {
                        v0 *= (1.0f + cs * cmb[col]);
                        v1 *= (1.0f + cs * cmb[col + 1]);
                    }
                    *(__half2*)&drow[col] = __floats2half2_rn(v0, v1);
                }
            }
        }
    } else {
        #pragma unroll
        for (int mt = 0; mt < 4; mt++) {
            #pragma unroll
            for (int half = 0; half < 2; half++) {
                const int row = mBase + wm * 64 + mt * 16 + lr + half * 8;
                const float bias = bout[row];
                float* drow = y + ((size_t)b * NDIM + row) * NPIX;
                #pragma unroll
                for (int nt = 0; nt < 4; nt++) {
                    const int col = nBase + wn * 32 + nt * 8 + 2 * lc;
                    drow[col]     = acc[mt][nt][half * 2]     + bias;
                    drow[col + 1] = acc[mt][nt][half * 2 + 1] + bias;
                }
            }
        }
    }
}

// ============================================================================
// K2 (f16 tensor): kv[d][e] = sum_n k[d][n]*v[e][n]; ksum[d] = sum_n k[d][n].
// k,v half in gmem. A = k [d][n] row-major (ldm non-trans).
// B = v [e][n] = B^T storage -> non-trans ldmatrix == trans-of-[k][n] frags.
// Smem rows: 128 halves + 8 pad = 272 B (17 = 1 mod 8, conflict-free).
// Warp grid: wm = wid&3 (d slab 16), wn = wid>>2 (e slab 32).
// ============================================================================
#define KVROW 136   // halves per smem row

__global__ __launch_bounds__(256) void kv_f16_kernel()
{
    __shared__ __half ks[64 * KVROW];
    __shared__ __half vs[64 * KVROW];

    const int pair = blockIdx.y;
    const int b = pair >> 3, h = pair & 7;
    const int n0 = blockIdx.x * 1024;
    const __half* kp = g_kh + ((size_t)b * HID + h * DHEAD) * NPIX;
    const __half* vp = g_vh + ((size_t)b * HID + h * DHEAD) * NPIX;

    const int tid  = threadIdx.x;
    const int wid  = tid >> 5;
    const int lane = tid & 31;
    const int lr   = lane >> 2;
    const int lc   = lane & 3;
    const int wm   = wid & 3;
    const int wn   = wid >> 2;

    const uint32_t sbk = (uint32_t)__cvta_generic_to_shared(ks);
    const uint32_t sbv = (uint32_t)__cvta_generic_to_shared(vs);

    // ldmatrix bases
    const uint32_t aLm = sbk + ((wm * 16 + (lane & 15)) * KVROW) * 2 + (lane >> 4) * 16;
    // B: row = e, bit4 of lane -> +8 e-rows, bit3 -> +16 B k-offset
    const uint32_t bLm = sbv + ((wn * 32 + (lane & 7) + ((lane >> 4) * 8)) * KVROW) * 2
                             + ((lane >> 3) & 1) * 16;

    float acc[4][4];
    #pragma unroll
    for (int nt = 0; nt < 4; nt++)
        #pragma unroll
        for (int i = 0; i < 4; i++) acc[nt][i] = 0.0f;
    float ksp[4] = {0.0f, 0.0f, 0.0f, 0.0f};

    for (int t = 0; t < 8; t++) {
        const int nb = n0 + t * 128;
        #pragma unroll
        for (int r = 0; r < 4; r++) {
            int li  = tid + r * 256;
            int row = li >> 4;          // 0..63
            int ch  = li & 15;          // 16B chunk (8 halves)
            uint4 kd = *(const uint4*)&kp[(size_t)row * NPIX + nb + ch * 8];
            *(uint4*)&ks[row * KVROW + ch * 8] = kd;
            const __half2* kh2 = (const __half2*)&kd;
            float2 s0 = __half22float2(kh2[0]);
            float2 s1 = __half22float2(kh2[1]);
            float2 s2 = __half22float2(kh2[2]);
            float2 s3 = __half22float2(kh2[3]);
            ksp[r] += (s0.x + s0.y) + (s1.x + s1.y) + (s2.x + s2.y) + (s3.x + s3.y);
            uint4 vd = *(const uint4*)&vp[(size_t)row * NPIX + nb + ch * 8];
            *(uint4*)&vs[row * KVROW + ch * 8] = vd;
        }
        __syncthreads();
        #pragma unroll
        for (int kk = 0; kk < 8; kk++) {           // 8 k16 steps per 128-chunk
            uint32_t a0, a1, a2, a3;
            ldm_x4(a0, a1, a2, a3, aLm + kk * 32);
            uint32_t bf[4][2];
            #pragma unroll
            for (int g = 0; g < 2; g++)            // e-16 slabs
                ldm_x4(bf[2 * g][0], bf[2 * g][1], bf[2 * g + 1][0], bf[2 * g + 1][1],
                       bLm + g * 16 * KVROW * 2 + kk * 32);
            #pragma unroll
            for (int nt = 0; nt < 4; nt++)
                mma_f16(acc[nt], a0, a1, a2, a3, bf[nt][0], bf[nt][1]);
        }
        __syncthreads();
    }

    #pragma unroll
    for (int r = 0; r < 4; r++) {
        float s = ksp[r];
        s += __shfl_xor_sync(0xffffffffu, s, 8);
        s += __shfl_xor_sync(0xffffffffu, s, 4);
        s += __shfl_xor_sync(0xffffffffu, s, 2);
        s += __shfl_xor_sync(0xffffffffu, s, 1);
        if ((tid & 15) == 0)
            atomicAdd(&g_ksum[(size_t)pair * 64 + ((tid + r * 256) >> 4)], s);
    }

    float* kvp = g_kv + (size_t)pair * 4096;
    #pragma unroll
    for (int nt = 0; nt < 4; nt++) {
        int e = wn * 32 + nt * 8 + 2 * lc;
        int d = wm * 16 + lr;
        atomicAdd(&kvp[d * 64 + e],           acc[nt][0]);
        atomicAdd(&kvp[d * 64 + e + 1],       acc[nt][1]);
        atomicAdd(&kvp[(d + 8) * 64 + e],     acc[nt][2]);
        atomicAdd(&kvp[(d + 8) * 64 + e + 1], acc[nt][3]);
    }
}

// ============================================================================
// K3 (f16 tensor): out[e][n] = z[n] * sum_d kv[d][e]*q[d][n].
// A = kv^T staged as half [e][72] (144 B rows). B = q half [d][264] (528 B rows).
// z computed fp32. Output g_oh half.
// ============================================================================
#define KVTROW 72    // halves
#define QROW 264     // halves

__global__ __launch_bounds__(256) void attn_f16_kernel()
{
    __shared__ __half kvt[64 * KVTROW];
    __shared__ __half qs[64 * QROW];
    __shared__ float  zs[256];
    __shared__ float  ksums[64];

    const int pair = blockIdx.y;
    const int b = pair >> 3, h = pair & 7;
    const int nB  = blockIdx.x * 256;
    const int tid = threadIdx.x;
    const int wid = tid >> 5;
    const int lane = tid & 31;
    const int lr = lane >> 2;
    const int lc = lane & 3;

    const float* kvp = g_kv + (size_t)pair * 4096;
    #pragma unroll
    for (int r = 0; r < 16; r++) {
        int i = tid + r * 256;
        int d = i >> 6, e = i & 63;
        kvt[e * KVTROW + d] = __float2half_rn(kvp[i]);
    }
    if (tid < 64) ksums[tid] = g_ksum[(size_t)pair * 64 + tid];

    const __half* qp = g_qh + ((size_t)b * HID + h * DHEAD) * NPIX + nB;
    #pragma unroll
    for (int r = 0; r < 8; r++) {
        int li = tid + r * 256;
        int d  = li >> 5;             // 0..63
        int c8 = (li & 31) * 8;       // 0..248
        uint4 qv = *(const uint4*)&qp[(size_t)d * NPIX + c8];
        *(uint4*)&qs[d * QROW + c8] = qv;
    }
    __syncthreads();

    {
        float denom = 1e-6f;
        #pragma unroll 16
        for (int d = 0; d < 64; d++)
            denom += __half2float(qs[d * QROW + tid]) * ksums[d];
        zs[tid] = 1.0f / denom;
    }
    __syncthreads();

    const uint32_t sbA = (uint32_t)__cvta_generic_to_shared(kvt);
    const uint32_t sbB = (uint32_t)__cvta_generic_to_shared(qs);
    const uint32_t aLm = sbA + ((lane & 15) * KVTROW) * 2 + (lane >> 4) * 16;
    const uint32_t bLm = sbB + ((lane & 15) * QROW) * 2
                             + (wid * 32 + (lane >> 4) * 8) * 2;

    float acc[4][4][4];
    #pragma unroll
    for (int mt = 0; mt < 4; mt++)
        #pragma unroll
        for (int nt = 0; nt < 4; nt++)
            #pragma unroll
            for (int i = 0; i < 4; i++) acc[mt][nt][i] = 0.0f;

    #pragma unroll
    for (int kk = 0; kk < 4; kk++) {               // 4 k16 steps over d=64
        uint32_t af[4][4];
        #pragma unroll
        for (int mt = 0; mt < 4; mt++)
            ldm_x4(af[mt][0], af[mt][1], af[mt][2], af[mt][3],
                   aLm + mt * 16 * KVTROW * 2 + kk * 32);
        uint32_t bf[4][2];
        #pragma unroll
        for (int g = 0; g < 2; g++)
            ldm_x4t(bf[2 * g][0], bf[2 * g][1], bf[2 * g + 1][0], bf[2 * g + 1][1],
                    bLm + kk * 16 * QROW * 2 + g * 32);
        #pragma unroll
        for (int nt = 0; nt < 4; nt++)
            #pragma unroll
            for (int mt = 0; mt < 4; mt++)
                mma_f16(acc[mt][nt], af[mt][0], af[mt][1], af[mt][2], af[mt][3],
                        bf[nt][0], bf[nt][1]);
    }

    __half* ob = g_oh + ((size_t)b * HID + h * DHEAD) * NPIX + nB;
    #pragma unroll
    for (int mt = 0; mt < 4; mt++) {
        #pragma unroll
        for (int half = 0; half < 2; half++) {
            int e = mt * 16 + lr + half * 8;
            __half* orow = ob + (size_t)e * NPIX;
            #pragma unroll
            for (int nt = 0; nt < 4; nt++) {
                int nloc = wid * 32 + nt * 8 + 2 * lc;
                *(__half2*)&orow[nloc] = __floats2half2_rn(
                    acc[mt][nt][half * 2]     * zs[nloc],
                    acc[mt][nt][half * 2 + 1] * zs[nloc + 1]);
            }
        }
    }
}

// ---------------- launch ----------------------------------------------------
extern "C" void kernel_launch(void* const* d_in, const int* in_sizes, int n_in,
                              void* d_out, int out_size)
{
    const float* x    = (const float*)d_in[0];
    const float* cm   = (const float*)d_in[1];
    const float* Wqkv = (const float*)d_in[2];
    const float* Wout = (const float*)d_in[3];
    const float* bout = (const float*)d_in[4];
    const float* cs   = (const float*)d_in[5];
    float* y = (float*)d_out;

    cudaFuncSetAttribute(gemm_f16_kernel<NDIM, 0>,
                         cudaFuncAttributeMaxDynamicSharedMemorySize, GEMM_SMEM);
    cudaFuncSetAttribute(gemm_f16_kernel<HID, 1>,
                         cudaFuncAttributeMaxDynamicSharedMemorySize, GEMM_SMEM);

    __half *xh, *wqkvh, *wouth, *oh;
    cudaGetSymbolAddress((void**)&xh, g_xh);
    cudaGetSymbolAddress((void**)&wqkvh, g_wqkvh);
    cudaGetSymbolAddress((void**)&wouth, g_wouth);
    cudaGetSymbolAddress((void**)&oh, g_oh);

    // converts (+ fused accumulator zeroing)
    {
        int n4 = BATCH * NDIM * NPIX / 4;
        convert_x_zero_kernel<<<(n4 + 255) / 256, 256>>>((const float4*)x, (__half2*)xh, n4);
        n4 = M1 * NDIM / 4;
        f32_to_f16_kernel<<<(n4 + 255) / 256, 256>>>((const float4*)Wqkv, (__half2*)wqkvh, n4);
        n4 = NDIM * HID / 4;
        f32_to_f16_kernel<<<(n4 + 255) / 256, 256>>>((const float4*)Wout, (__half2*)wouth, n4);
    }

    {
        dim3 grid(NPIX / 128, M1 / 128, BATCH);   // 32 x 12 x 8
        gemm_f16_kernel<NDIM, 0><<<grid, 256, GEMM_SMEM>>>(wqkvh, xh, cm, cs, nullptr, nullptr);
    }
    {
        dim3 grid(NPIX / 1024, BATCH * NHEADS);   // 4 x 64
        kv_f16_kernel<<<grid, 256>>>();
    }
    {
        dim3 grid(NPIX / 256, BATCH * NHEADS);    // 16 x 64
        attn_f16_kernel<<<grid, 256>>>();
    }
    {
        dim3 grid(NPIX / 128, NDIM / 128, BATCH); // 32 x 2 x 8
        gemm_f16_kernel<HID, 1><<<grid, 256, GEMM_SMEM>>>(wouth, oh, nullptr, nullptr, bout, y);
    }
}